// round 3
// baseline (speedup 1.0000x reference)
#include <cuda_runtime.h>
#include <cstdint>

#define IN 8192
#define OUT 8192
#define RW 1024              // packed int32 rows (IN/8)
#define TPB 256              // 8 warps
#define OPB 16               // outputs per block -> grid = 512
#define NRG 64               // concurrent row-groups per block
#define NIT (RW / NRG)       // 16 iterations per thread

// Exponent-OR dequant, 3 shifts per word:
//   window [11:15): float = 1 + v/4096  -> x' = x*4096
//   window [15:19): float = 1 + v/256   -> x' = x*256
//   window [19:23): float = 1 + v/16    -> x' = x*16
// fma.rn.f32x2(acc, x', t) accumulates x'*1 + x*v; Sum(x') bias subtracted at end.
#define M12 0x00007800u
#define M8  0x00078000u
#define M4  0x00780000u

__device__ __forceinline__ void dq_fma2(unsigned long long& acc,
                                        unsigned slo, unsigned mlo,
                                        unsigned shi, unsigned mhi,
                                        unsigned long long xp) {
    asm("{\n\t"
        ".reg .b32 lo, hi;\n\t"
        ".reg .b64 v;\n\t"
        "lop3.b32 lo, %1, %2, 0x3F800000, 0xEA;\n\t"
        "lop3.b32 hi, %3, %4, 0x3F800000, 0xEA;\n\t"
        "mov.b64 v, {lo, hi};\n\t"
        "fma.rn.f32x2 %0, %5, v, %0;\n\t"
        "}"
        : "+l"(acc) : "r"(slo), "r"(mlo), "r"(shi), "r"(mhi), "l"(xp));
}

__device__ __forceinline__ float acc_sum(unsigned long long a, unsigned long long b) {
    return (__uint_as_float((unsigned)(a & 0xffffffffu)) +
            __uint_as_float((unsigned)(a >> 32))) +
           (__uint_as_float((unsigned)(b & 0xffffffffu)) +
            __uint_as_float((unsigned)(b >> 32)));
}

__global__ __launch_bounds__(TPB, 4)
void qmv_kernel(const float* __restrict__ x, const int* __restrict__ qw,
                const float* __restrict__ scales, const float* __restrict__ zeros,
                const float* __restrict__ bias, float* __restrict__ out) {
    __shared__ ulonglong2 xs2[IN / 4];   // pre-scaled x' pairs, 32 KB
    __shared__ float red[NRG][OPB];      // 4 KB
    __shared__ float r2[16][OPB];        // 1 KB
    __shared__ float rs[8], rsp[8];

    const int tid  = threadIdx.x;
    const int lane = tid & 31;
    const int w    = tid >> 5;
    const int og   = lane & 3;                 // output quad 0..3 (16 outputs)
    const int rg   = (w << 3) | (lane >> 2);   // row-group 0..63

    // ---- stage x' pairs; scale pattern per k%8: 4096,256,16,4096,256,16,4096,256
    float sp = 0.f, spp = 0.f;
    const float4* xg = reinterpret_cast<const float4*>(x);
    #pragma unroll
    for (int i = tid; i < IN / 4; i += TPB) {
        float4 v = xg[i];
        sp += (v.x + v.y) + (v.z + v.w);
        float p0, p1, p2, p3;
        if (i & 1) {  // k%8 = 4..7 -> scales 256,16,4096,256
            p0 = v.x * 256.f;  p1 = v.y * 16.f;
            p2 = v.z * 4096.f; p3 = v.w * 256.f;
        } else {      // k%8 = 0..3 -> scales 4096,256,16,4096
            p0 = v.x * 4096.f; p1 = v.y * 256.f;
            p2 = v.z * 16.f;   p3 = v.w * 4096.f;
        }
        spp += (p0 + p1) + (p2 + p3);
        unsigned long long lo = ((unsigned long long)__float_as_uint(p1) << 32) |
                                __float_as_uint(p0);
        unsigned long long hi = ((unsigned long long)__float_as_uint(p3) << 32) |
                                __float_as_uint(p2);
        xs2[i] = make_ulonglong2(lo, hi);
    }
    #pragma unroll
    for (int o = 16; o > 0; o >>= 1) {
        sp  += __shfl_down_sync(0xffffffffu, sp, o);
        spp += __shfl_down_sync(0xffffffffu, spp, o);
    }
    if (lane == 0) { rs[w] = sp; rsp[w] = spp; }
    __syncthreads();

    // ---- main loop: 4 outputs (uint4), rows rg + 64*i, prefetch next iter ----
    const uint4* qp = reinterpret_cast<const uint4*>(qw) +
                      (size_t)rg * (OUT / 4) + blockIdx.x * (OPB / 4) + og;
    const size_t qstride = (size_t)NRG * (OUT / 4);

    unsigned long long a0A = 0, a0B = 0, a1A = 0, a1B = 0;
    unsigned long long a2A = 0, a2B = 0, a3A = 0, a3B = 0;

    uint4 wv = qp[0];
    ulonglong2 xA = xs2[2 * rg];
    ulonglong2 xB = xs2[2 * rg + 1];

    #pragma unroll 4
    for (int i = 0; i < NIT; i++) {
        uint4 wn;
        ulonglong2 xAn, xBn;
        if (i + 1 < NIT) {
            wn  = qp[(size_t)(i + 1) * qstride];
            int rn = rg + ((i + 1) << 6);
            xAn = xs2[2 * rn];
            xBn = xs2[2 * rn + 1];
        }
        unsigned s1, s2, s3;
        // word 0
        s1 = wv.x << 11; s2 = wv.x >> 1; s3 = wv.x >> 13;
        dq_fma2(a0A, s1, M12, s1, M8, xA.x);   // nibbles 0,1
        dq_fma2(a0B, s1, M4,  s2, M12, xA.y);  // nibbles 2,3
        dq_fma2(a0A, s2, M8,  s2, M4,  xB.x);  // nibbles 4,5
        dq_fma2(a0B, s3, M12, s3, M8,  xB.y);  // nibbles 6,7
        // word 1
        s1 = wv.y << 11; s2 = wv.y >> 1; s3 = wv.y >> 13;
        dq_fma2(a1A, s1, M12, s1, M8, xA.x);
        dq_fma2(a1B, s1, M4,  s2, M12, xA.y);
        dq_fma2(a1A, s2, M8,  s2, M4,  xB.x);
        dq_fma2(a1B, s3, M12, s3, M8,  xB.y);
        // word 2
        s1 = wv.z << 11; s2 = wv.z >> 1; s3 = wv.z >> 13;
        dq_fma2(a2A, s1, M12, s1, M8, xA.x);
        dq_fma2(a2B, s1, M4,  s2, M12, xA.y);
        dq_fma2(a2A, s2, M8,  s2, M4,  xB.x);
        dq_fma2(a2B, s3, M12, s3, M8,  xB.y);
        // word 3
        s1 = wv.w << 11; s2 = wv.w >> 1; s3 = wv.w >> 13;
        dq_fma2(a3A, s1, M12, s1, M8, xA.x);
        dq_fma2(a3B, s1, M4,  s2, M12, xA.y);
        dq_fma2(a3A, s2, M8,  s2, M4,  xB.x);
        dq_fma2(a3B, s3, M12, s3, M8,  xB.y);

        wv = wn; xA = xAn; xB = xBn;
    }

    {
        float4 f = make_float4(acc_sum(a0A, a0B), acc_sum(a1A, a1B),
                               acc_sum(a2A, a2B), acc_sum(a3A, a3B));
        *reinterpret_cast<float4*>(&red[rg][og * 4]) = f;
    }
    __syncthreads();

    // ---- reduce 64 row-groups per output ----
    {
        int o = tid & 15, seg = tid >> 4;   // 16 segs x 16 outputs
        float s = 0.f;
        #pragma unroll
        for (int j = 0; j < 4; j++) s += red[seg * 4 + j][o];
        r2[seg][o] = s;
    }
    __syncthreads();

    if (tid < OPB) {
        float dot = 0.f;
        #pragma unroll
        for (int j = 0; j < 16; j++) dot += r2[j][tid];
        float sx = 0.f, sxp = 0.f;
        #pragma unroll
        for (int i = 0; i < 8; i++) { sx += rs[i]; sxp += rsp[i]; }
        dot -= sxp;   // remove implicit-1.0 bias
        int o = blockIdx.x * OPB + tid;
        out[o] = bias[o] + scales[o] * dot - zeros[o] * sx;
    }
}

extern "C" void kernel_launch(void* const* d_in, const int* in_sizes, int n_in,
                              void* d_out, int out_size) {
    const float* x      = (const float*)d_in[0];
    const int*   qw     = (const int*)d_in[1];
    const float* scales = (const float*)d_in[2];
    const float* zeros  = (const float*)d_in[3];
    const float* bias   = (const float*)d_in[4];
    float* out = (float*)d_out;

    qmv_kernel<<<OUT / OPB, TPB>>>(x, qw, scales, zeros, bias, out);
}